// round 3
// baseline (speedup 1.0000x reference)
#include <cuda_runtime.h>
#include <math.h>

constexpr int N_OSC  = 2048;
constexpr int N_SAMP = 16384;
constexpr int LAT    = 32;
constexpr int HALF   = N_OSC * LAT;               // 65536

constexpr int OSC_CHUNK  = 64;
constexpr int SAMP_CHUNK = 1024;
constexpr int THREADS    = 256;
constexpr int SPT        = 4;                      // contiguous samples per thread
constexpr int N_OSC_BLK  = N_OSC / OSC_CHUNK;      // 32
constexpr int N_SAMP_BLK = N_SAMP / SAMP_CHUNK;    // 16

// Partial signals per oscillator block: 32 x 16384 floats = 2 MB
__device__ float g_scratch[N_OSC_BLK * N_SAMP];

// -----------------------------------------------------------------------------
// Fused main kernel. Block = 64 oscillators x 1024 samples, 256 threads.
//
// Prologue (warp-parallel, replaces old prep_kernel):
//   lane k of a warp owns breakpoint k of one oscillator. Exclusive warp scan
//   (double) of t_j = 256*(fp[j]+fp[j+1]) gives C_k; base = pi*C_k reduced
//   mod 2pi in double so the main-loop phase argument stays small (|Q|<~250).
//
// Main loop phase (all pre-scaled by pi):
//   Q = base_red + pi*(m+1)*fp[k] + pi*(m+1)^2/1024 * df
//   contribution = __sinf(Q) * (ap[k] + w*da)
// Each thread owns 4 CONTIGUOUS samples; segment boundaries (256+512k) are
// 4-aligned so all 4 share segment k -> per-oscillator smem loads hoisted.
// -----------------------------------------------------------------------------
__global__ __launch_bounds__(THREADS, 4)
void osc_kernel(const float* __restrict__ latent) {
    __shared__ float4 s_pack[OSC_CHUNK * LAT];   // (fp, df, ap, da)  32 KB
    __shared__ float  s_base[OSC_CHUNK * LAT];   // pi*C_k mod 2pi     8 KB

    const int tid     = threadIdx.x;
    const int lane    = tid & 31;
    const int warp    = tid >> 5;
    const int oscBase = blockIdx.y * OSC_CHUNK;

    // ---- prologue: 8 warps x 8 oscillators each ----
    const double PI_D     = 3.141592653589793238462643383;
    const double TWOPI_D  = 6.283185307179586476925286767;
    const double INV2PI_D = 0.159154943091895335768883763;
#pragma unroll
    for (int j = 0; j < OSC_CHUNK / 8; ++j) {
        const int o  = warp * (OSC_CHUNK / 8) + j;
        const int go = oscBase + o;
        const float f = fabsf(latent[(size_t)(N_OSC + go) * LAT + lane]);
        const float a = fabsf(latent[(size_t)go * LAT + lane]);
        const float fn = __shfl_down_sync(0xffffffffu, f, 1);
        const float an = __shfl_down_sync(0xffffffffu, a, 1);
        const float df = (lane < 31) ? (fn - f) : 0.0f;
        const float da = (lane < 31) ? (an - a) : 0.0f;
        // exclusive scan of t_k = 256*(fp[k]+fp[k+1])
        double t  = (lane < 31) ? 256.0 * ((double)f + (double)fn) : 0.0;
        double sc = t;
#pragma unroll
        for (int d = 1; d < 32; d <<= 1) {
            double u = __shfl_up_sync(0xffffffffu, sc, d);
            if (lane >= d) sc += u;
        }
        const double f0 = __shfl_sync(0xffffffffu, (double)f, 0);
        const double C  = 256.0 * f0 + (sc - t);          // C_k (exclusive)
        double ph = PI_D * C;
        ph -= TWOPI_D * rint(ph * INV2PI_D);              // reduce to [-pi, pi]
        s_pack[o * LAT + lane] = make_float4(f, df, a, da);
        s_base[o * LAT + lane] = (float)ph;
    }
    __syncthreads();

    // ---- per-thread sample constants (pre-scaled by pi) ----
    const float PI_F = 3.14159265358979323846f;
    const int i0 = blockIdx.x * SAMP_CHUNK + tid * SPT;
    int k;
    float c1q[SPT], c2q[SPT], w[SPT];
    if (i0 < 256) {                       // pre: Q = base0 + pi*(i-255)*fp0
        k = 0;
#pragma unroll
        for (int s = 0; s < SPT; ++s) { c1q[s] = PI_F * (float)(i0 + s - 255); c2q[s] = 0.0f; w[s] = 0.0f; }
    } else if (i0 >= 16128) {             // post: Q = base31 + pi*(i-16127)*fp31
        k = 31;
#pragma unroll
        for (int s = 0; s < SPT; ++s) { c1q[s] = PI_F * (float)(i0 + s - 16127); c2q[s] = 0.0f; w[s] = 0.0f; }
    } else {                              // segment k, offset m
        k = (i0 - 256) >> 9;
        const int m0 = (i0 - 256) & 511;
#pragma unroll
        for (int s = 0; s < SPT; ++s) {
            const float mp1 = (float)(m0 + s + 1);
            c1q[s] = PI_F * mp1;
            c2q[s] = PI_F * mp1 * mp1 * (1.0f / 1024.0f);
            w[s]   = ((float)(m0 + s) + 0.5f) * (1.0f / 512.0f);
        }
    }

    // ---- main loop: 5 fma-pipe ops + 1 MUFU per (osc,sample) ----
    float acc[SPT] = {0.0f, 0.0f, 0.0f, 0.0f};
    const float4* pk = &s_pack[k];
    const float*  bk = &s_base[k];
#pragma unroll 4
    for (int o = 0; o < OSC_CHUNK; ++o) {
        const float4 p  = pk[o * LAT];    // (fp, df, ap, da)
        const float  bq = bk[o * LAT];
#pragma unroll
        for (int s = 0; s < SPT; ++s) {
            const float Q   = fmaf(c2q[s], p.y, fmaf(c1q[s], p.x, bq));
            const float sv  = __sinf(Q);
            const float amp = fmaf(w[s], p.w, p.z);
            acc[s] = fmaf(sv, amp, acc[s]);
        }
    }

    *reinterpret_cast<float4*>(&g_scratch[blockIdx.y * N_SAMP + i0]) =
        make_float4(acc[0], acc[1], acc[2], acc[3]);
}

// -----------------------------------------------------------------------------
// Epilogue (float4-vectorized):
//   out[0:16384]            = mean over 32 partial rows / 2048
//   out[16384:16384+65536]  = |latent[65536:131072]|  (freq_params)
//   out[16384+65536:...]    = |latent[0:65536]|       (amp_params)
// -----------------------------------------------------------------------------
__global__ void epilogue_kernel(const float* __restrict__ latent, float* __restrict__ out) {
    const int t = blockIdx.x * blockDim.x + threadIdx.x;   // 0..36863
    if (t < N_SAMP / 4) {
        const int i = t * 4;
        float4 acc = make_float4(0.f, 0.f, 0.f, 0.f);
#pragma unroll
        for (int b = 0; b < N_OSC_BLK; ++b) {
            const float4 v = *reinterpret_cast<const float4*>(&g_scratch[b * N_SAMP + i]);
            acc.x += v.x; acc.y += v.y; acc.z += v.z; acc.w += v.w;
        }
        const float sc = 1.0f / (float)N_OSC;
        *reinterpret_cast<float4*>(&out[i]) =
            make_float4(acc.x * sc, acc.y * sc, acc.z * sc, acc.w * sc);
    } else if (t < N_SAMP / 4 + 2 * HALF / 4) {
        const int idx = (t - N_SAMP / 4) * 4;              // 0..131068, 4-aligned
        const int src = (idx < HALF) ? (HALF + idx) : (idx - HALF);
        const float4 v = *reinterpret_cast<const float4*>(&latent[src]);
        *reinterpret_cast<float4*>(&out[N_SAMP + idx]) =
            make_float4(fabsf(v.x), fabsf(v.y), fabsf(v.z), fabsf(v.w));
    }
}

extern "C" void kernel_launch(void* const* d_in, const int* in_sizes, int n_in,
                              void* d_out, int out_size) {
    const float* latent = (const float*)d_in[n_in - 1];
    for (int i = 0; i < n_in; ++i) {
        if (in_sizes[i] == 2 * HALF) { latent = (const float*)d_in[i]; break; }
    }
    float* out = (float*)d_out;

    dim3 grid(N_SAMP_BLK, N_OSC_BLK);                       // 16 x 32 = 512 blocks
    osc_kernel<<<grid, THREADS>>>(latent);

    const int epi_threads = N_SAMP / 4 + 2 * HALF / 4;      // 36864
    epilogue_kernel<<<epi_threads / 256, 256>>>(latent, out);
}

// round 4
// speedup vs baseline: 2.3649x; 2.3649x over previous
#include <cuda_runtime.h>
#include <math.h>

constexpr int N_OSC  = 2048;
constexpr int N_SAMP = 16384;
constexpr int LAT    = 32;
constexpr int HALF   = N_OSC * LAT;               // 65536

constexpr int OSC_CHUNK  = 32;
constexpr int SAMP_CHUNK = 1024;
constexpr int THREADS    = 256;
constexpr int SPT        = 4;                      // contiguous samples per thread
constexpr int N_OSC_BLK  = N_OSC / OSC_CHUNK;      // 64
constexpr int N_SAMP_BLK = N_SAMP / SAMP_CHUNK;    // 16

// Per-(osc,k): (fp[k], fp[k+1]-fp[k], ap[k], ap[k+1]-ap[k]); base = pi*C_k mod 2pi
__device__ float4 g_pack[N_OSC * LAT];
__device__ float  g_base[N_OSC * LAT];
// Partial signals per oscillator block: 64 x 16384 floats = 4 MB
__device__ float  g_scratch[N_OSC_BLK * N_SAMP];

// -----------------------------------------------------------------------------
// Prep: ONE WARP PER OSCILLATOR (lane = breakpoint k). fp64 exclusive shuffle
// scan of t_j = 256*(fp[j]+fp[j+1]) gives C_k; store pi*C_k reduced mod 2pi.
// 2048 warps -> fully parallel (was the 16.5us serial bottleneck in R2,
// and a register-pressure disaster when fused into osc_kernel in R3).
// -----------------------------------------------------------------------------
__global__ __launch_bounds__(256)
void prep_kernel(const float* __restrict__ latent) {
    const int lane = threadIdx.x & 31;
    const int o    = blockIdx.x * 8 + (threadIdx.x >> 5);

    const float f  = fabsf(latent[(size_t)(N_OSC + o) * LAT + lane]);
    const float a  = fabsf(latent[(size_t)o * LAT + lane]);
    const float fn = __shfl_down_sync(0xffffffffu, f, 1);
    const float an = __shfl_down_sync(0xffffffffu, a, 1);
    const float df = (lane < 31) ? (fn - f) : 0.0f;
    const float da = (lane < 31) ? (an - a) : 0.0f;

    double t  = (lane < 31) ? 256.0 * ((double)f + (double)fn) : 0.0;
    double sc = t;
#pragma unroll
    for (int d = 1; d < 32; d <<= 1) {
        const double u = __shfl_up_sync(0xffffffffu, sc, d);
        if (lane >= d) sc += u;
    }
    const float  f0 = __shfl_sync(0xffffffffu, f, 0);
    const double C  = 256.0 * (double)f0 + (sc - t);   // exclusive prefix C_k

    const double PI_D     = 3.141592653589793238462643383;
    const double TWOPI_D  = 6.283185307179586476925286767;
    const double INV2PI_D = 0.159154943091895335768883763;
    double ph = PI_D * C;
    ph -= TWOPI_D * rint(ph * INV2PI_D);               // [-pi, pi]

    g_pack[o * LAT + lane] = make_float4(f, df, a, da);
    g_base[o * LAT + lane] = (float)ph;
}

// -----------------------------------------------------------------------------
// Main: block = 32 oscillators x 1024 samples (R2's winning occupancy config).
// Inner loop (pre-scaled by pi): Q = base + c1q*fp[k] + c2q*df;
// contribution = __sinf(Q) * (ap[k] + w*da)  -> 4 FMA-pipe ops + 1 MUFU.
// Each thread: 4 CONTIGUOUS samples (segment boundaries 4-aligned -> all 4
// share k -> per-oscillator smem loads hoisted: LDS.128 + LDS.32, broadcast).
// -----------------------------------------------------------------------------
__global__ __launch_bounds__(THREADS, 4)
void osc_kernel() {
    __shared__ float4 s_pack[OSC_CHUNK * LAT];   // 16 KB
    __shared__ float  s_base[OSC_CHUNK * LAT];   //  4 KB

    const int tid     = threadIdx.x;
    const int oscBase = blockIdx.y * OSC_CHUNK;

#pragma unroll
    for (int j = tid; j < OSC_CHUNK * LAT; j += THREADS) {
        s_pack[j] = g_pack[oscBase * LAT + j];
        s_base[j] = g_base[oscBase * LAT + j];
    }
    __syncthreads();

    const float PI_F = 3.14159265358979323846f;
    const int i0 = blockIdx.x * SAMP_CHUNK + tid * SPT;
    int k;
    float c1q[SPT], c2q[SPT], w[SPT];
    if (i0 < 256) {                       // pre: Q = base0 + pi*(i-255)*fp0
        k = 0;
#pragma unroll
        for (int s = 0; s < SPT; ++s) { c1q[s] = PI_F * (float)(i0 + s - 255); c2q[s] = 0.0f; w[s] = 0.0f; }
    } else if (i0 >= 16128) {             // post
        k = 31;
#pragma unroll
        for (int s = 0; s < SPT; ++s) { c1q[s] = PI_F * (float)(i0 + s - 16127); c2q[s] = 0.0f; w[s] = 0.0f; }
    } else {                              // segment k, offset m
        k = (i0 - 256) >> 9;
        const int m0 = (i0 - 256) & 511;
#pragma unroll
        for (int s = 0; s < SPT; ++s) {
            const float mp1 = (float)(m0 + s + 1);
            c1q[s] = PI_F * mp1;
            c2q[s] = PI_F * mp1 * mp1 * (1.0f / 1024.0f);
            w[s]   = ((float)(m0 + s) + 0.5f) * (1.0f / 512.0f);
        }
    }

    float acc[SPT] = {0.0f, 0.0f, 0.0f, 0.0f};
    const float4* pk = &s_pack[k];
    const float*  bk = &s_base[k];
#pragma unroll 4
    for (int o = 0; o < OSC_CHUNK; ++o) {
        const float4 p  = pk[o * LAT];    // (fp, df, ap, da)
        const float  bq = bk[o * LAT];
#pragma unroll
        for (int s = 0; s < SPT; ++s) {
            const float Q   = fmaf(c2q[s], p.y, fmaf(c1q[s], p.x, bq));
            const float sv  = __sinf(Q);
            const float amp = fmaf(w[s], p.w, p.z);
            acc[s] = fmaf(sv, amp, acc[s]);
        }
    }

    *reinterpret_cast<float4*>(&g_scratch[blockIdx.y * N_SAMP + i0]) =
        make_float4(acc[0], acc[1], acc[2], acc[3]);
}

// -----------------------------------------------------------------------------
// Epilogue, parallelized 8x over the row reduction:
//   signal: 8 threads per 4-sample group; thread `sub` sums rows 8*sub..8*sub+7
//           (float4 loads), then 3-step shfl_xor butterfly within the octet.
//   params: |latent| passthroughs, float4.
// -----------------------------------------------------------------------------
__global__ void epilogue_kernel(const float* __restrict__ latent, float* __restrict__ out) {
    const int t = blockIdx.x * blockDim.x + threadIdx.x;   // 0..65535
    if (t < N_SAMP * 2) {                                   // 32768 signal threads
        const int g   = t >> 3;                             // sample group (4 samples)
        const int sub = t & 7;                              // row octet
        const int i   = g * 4;
        float4 acc = make_float4(0.f, 0.f, 0.f, 0.f);
#pragma unroll
        for (int r = 0; r < 8; ++r) {
            const float4 v = *reinterpret_cast<const float4*>(
                &g_scratch[(sub * 8 + r) * N_SAMP + i]);
            acc.x += v.x; acc.y += v.y; acc.z += v.z; acc.w += v.w;
        }
#pragma unroll
        for (int d = 4; d >= 1; d >>= 1) {
            acc.x += __shfl_xor_sync(0xffffffffu, acc.x, d);
            acc.y += __shfl_xor_sync(0xffffffffu, acc.y, d);
            acc.z += __shfl_xor_sync(0xffffffffu, acc.z, d);
            acc.w += __shfl_xor_sync(0xffffffffu, acc.w, d);
        }
        if (sub == 0) {
            const float sc = 1.0f / (float)N_OSC;
            *reinterpret_cast<float4*>(&out[i]) =
                make_float4(acc.x * sc, acc.y * sc, acc.z * sc, acc.w * sc);
        }
    } else {                                                // 32768 param threads
        const int idx = (t - N_SAMP * 2) * 4;               // 0..131068
        const int src = (idx < HALF) ? (HALF + idx) : (idx - HALF);
        const float4 v = *reinterpret_cast<const float4*>(&latent[src]);
        *reinterpret_cast<float4*>(&out[N_SAMP + idx]) =
            make_float4(fabsf(v.x), fabsf(v.y), fabsf(v.z), fabsf(v.w));
    }
}

extern "C" void kernel_launch(void* const* d_in, const int* in_sizes, int n_in,
                              void* d_out, int out_size) {
    const float* latent = (const float*)d_in[n_in - 1];
    for (int i = 0; i < n_in; ++i) {
        if (in_sizes[i] == 2 * HALF) { latent = (const float*)d_in[i]; break; }
    }
    float* out = (float*)d_out;

    prep_kernel<<<N_OSC / 8, 256>>>(latent);
    dim3 grid(N_SAMP_BLK, N_OSC_BLK);                       // 16 x 64 = 1024 blocks
    osc_kernel<<<grid, THREADS>>>();
    epilogue_kernel<<<(N_SAMP * 2 + 2 * HALF / 4) / 256, 256>>>(latent, out);
}

// round 5
// speedup vs baseline: 2.6210x; 1.1083x over previous
#include <cuda_runtime.h>
#include <math.h>

constexpr int N_OSC  = 2048;
constexpr int N_SAMP = 16384;
constexpr int LAT    = 32;
constexpr int HALF   = N_OSC * LAT;               // 65536

constexpr int OSC_CHUNK  = 32;
constexpr int SAMP_CHUNK = 1024;
constexpr int THREADS    = 256;
constexpr int SPT        = 4;                      // contiguous samples per thread
constexpr int N_OSC_BLK  = N_OSC / OSC_CHUNK;      // 64
constexpr int N_SAMP_BLK = N_SAMP / SAMP_CHUNK;    // 16

// Partial signals per oscillator block: 64 x 16384 floats = 4 MB
__device__ float g_scratch[N_OSC_BLK * N_SAMP];

// -----------------------------------------------------------------------------
// Fused main kernel. Block = 32 oscillators x 1024 samples, 256 threads.
//
// Prologue (pure fp32, ~300 cyc): each warp owns 4 oscillators; lane k owns
// breakpoint k. Exclusive fp32 shuffle-scan of t_j = 256*(fp[j]+fp[j+1])
// gives C_k; mod-2 reduction (C - 2*rintf(C/2)) is EXACT (Sterbenz), so
// base = pi*(C_k mod 2) in [-pi, pi]. fp32 scan error ~7e-4 -> ~7e-6 rel_err
// contribution (incoherent over 2048 oscillators, diluted by param norm).
//
// Main loop (pre-scaled by pi): Q = base + c1q*fp[k] + c2q*df;
// contribution = __sinf(Q) * (ap[k] + w*da)  -> 4 FMA-pipe + 1 MUFU.
// Each thread: 4 CONTIGUOUS samples (segment boundaries 4-aligned -> all 4
// share k -> per-oscillator smem loads hoisted: LDS.128 + LDS.32, broadcast).
// -----------------------------------------------------------------------------
__global__ __launch_bounds__(THREADS, 4)
void osc_kernel(const float* __restrict__ latent) {
    __shared__ float4 s_pack[OSC_CHUNK * LAT];   // (fp, df, ap, da)  16 KB
    __shared__ float  s_base[OSC_CHUNK * LAT];   // pi*(C_k mod 2)     4 KB

    const int tid     = threadIdx.x;
    const int lane    = tid & 31;
    const int warp    = tid >> 5;
    const int oscBase = blockIdx.y * OSC_CHUNK;
    const float PI_F  = 3.14159265358979323846f;

    // ---- fp32 prologue: 8 warps x 4 oscillators ----
#pragma unroll
    for (int j = 0; j < OSC_CHUNK / 8; ++j) {
        const int o  = warp * (OSC_CHUNK / 8) + j;
        const int go = oscBase + o;
        const float f  = fabsf(latent[(size_t)(N_OSC + go) * LAT + lane]);
        const float a  = fabsf(latent[(size_t)go * LAT + lane]);
        const float fn = __shfl_down_sync(0xffffffffu, f, 1);
        const float an = __shfl_down_sync(0xffffffffu, a, 1);
        const float df = (lane < 31) ? (fn - f) : 0.0f;
        const float da = (lane < 31) ? (an - a) : 0.0f;
        // exclusive scan of t_k = 256*(fp[k]+fp[k+1])
        const float t = (lane < 31) ? 256.0f * (f + fn) : 0.0f;
        float sc = t;
#pragma unroll
        for (int d = 1; d < 32; d <<= 1) {
            const float u = __shfl_up_sync(0xffffffffu, sc, d);
            if (lane >= d) sc += u;
        }
        const float f0 = __shfl_sync(0xffffffffu, f, 0);
        const float C  = fmaf(256.0f, f0, sc - t);        // exclusive prefix C_k
        const float r  = fmaf(-2.0f, rintf(0.5f * C), C); // C mod 2, exact, [-1,1]
        s_pack[o * LAT + lane] = make_float4(f, df, a, da);
        s_base[o * LAT + lane] = PI_F * r;
    }
    __syncthreads();

    // ---- per-thread sample constants (pre-scaled by pi) ----
    const int i0 = blockIdx.x * SAMP_CHUNK + tid * SPT;
    int k;
    float c1q[SPT], c2q[SPT], w[SPT];
    if (i0 < 256) {                       // pre: Q = base0 + pi*(i-255)*fp0
        k = 0;
#pragma unroll
        for (int s = 0; s < SPT; ++s) { c1q[s] = PI_F * (float)(i0 + s - 255); c2q[s] = 0.0f; w[s] = 0.0f; }
    } else if (i0 >= 16128) {             // post
        k = 31;
#pragma unroll
        for (int s = 0; s < SPT; ++s) { c1q[s] = PI_F * (float)(i0 + s - 16127); c2q[s] = 0.0f; w[s] = 0.0f; }
    } else {                              // segment k, offset m
        k = (i0 - 256) >> 9;
        const int m0 = (i0 - 256) & 511;
#pragma unroll
        for (int s = 0; s < SPT; ++s) {
            const float mp1 = (float)(m0 + s + 1);
            c1q[s] = PI_F * mp1;
            c2q[s] = PI_F * mp1 * mp1 * (1.0f / 1024.0f);
            w[s]   = ((float)(m0 + s) + 0.5f) * (1.0f / 512.0f);
        }
    }

    // ---- main loop: 4 FMA-pipe ops + 1 MUFU per (osc,sample) ----
    float acc[SPT] = {0.0f, 0.0f, 0.0f, 0.0f};
    const float4* pk = &s_pack[k];
    const float*  bk = &s_base[k];
#pragma unroll 4
    for (int o = 0; o < OSC_CHUNK; ++o) {
        const float4 p  = pk[o * LAT];    // (fp, df, ap, da)
        const float  bq = bk[o * LAT];
#pragma unroll
        for (int s = 0; s < SPT; ++s) {
            const float Q   = fmaf(c2q[s], p.y, fmaf(c1q[s], p.x, bq));
            const float sv  = __sinf(Q);
            const float amp = fmaf(w[s], p.w, p.z);
            acc[s] = fmaf(sv, amp, acc[s]);
        }
    }

    *reinterpret_cast<float4*>(&g_scratch[blockIdx.y * N_SAMP + i0]) =
        make_float4(acc[0], acc[1], acc[2], acc[3]);
}

// -----------------------------------------------------------------------------
// Epilogue: 8 threads per 4-sample group (each sums 8 rows, float4 loads),
// 3-step shfl_xor butterfly; plus |latent| passthroughs.
// -----------------------------------------------------------------------------
__global__ void epilogue_kernel(const float* __restrict__ latent, float* __restrict__ out) {
    const int t = blockIdx.x * blockDim.x + threadIdx.x;   // 0..65535
    if (t < N_SAMP * 2) {                                   // 32768 signal threads
        const int g   = t >> 3;
        const int sub = t & 7;
        const int i   = g * 4;
        float4 acc = make_float4(0.f, 0.f, 0.f, 0.f);
#pragma unroll
        for (int r = 0; r < 8; ++r) {
            const float4 v = *reinterpret_cast<const float4*>(
                &g_scratch[(sub * 8 + r) * N_SAMP + i]);
            acc.x += v.x; acc.y += v.y; acc.z += v.z; acc.w += v.w;
        }
#pragma unroll
        for (int d = 4; d >= 1; d >>= 1) {
            acc.x += __shfl_xor_sync(0xffffffffu, acc.x, d);
            acc.y += __shfl_xor_sync(0xffffffffu, acc.y, d);
            acc.z += __shfl_xor_sync(0xffffffffu, acc.z, d);
            acc.w += __shfl_xor_sync(0xffffffffu, acc.w, d);
        }
        if (sub == 0) {
            const float sc = 1.0f / (float)N_OSC;
            *reinterpret_cast<float4*>(&out[i]) =
                make_float4(acc.x * sc, acc.y * sc, acc.z * sc, acc.w * sc);
        }
    } else {                                                // 32768 param threads
        const int idx = (t - N_SAMP * 2) * 4;
        const int src = (idx < HALF) ? (HALF + idx) : (idx - HALF);
        const float4 v = *reinterpret_cast<const float4*>(&latent[src]);
        *reinterpret_cast<float4*>(&out[N_SAMP + idx]) =
            make_float4(fabsf(v.x), fabsf(v.y), fabsf(v.z), fabsf(v.w));
    }
}

extern "C" void kernel_launch(void* const* d_in, const int* in_sizes, int n_in,
                              void* d_out, int out_size) {
    const float* latent = (const float*)d_in[n_in - 1];
    for (int i = 0; i < n_in; ++i) {
        if (in_sizes[i] == 2 * HALF) { latent = (const float*)d_in[i]; break; }
    }
    float* out = (float*)d_out;

    dim3 grid(N_SAMP_BLK, N_OSC_BLK);                       // 16 x 64 = 1024 blocks
    osc_kernel<<<grid, THREADS>>>(latent);
    epilogue_kernel<<<(N_SAMP * 2 + 2 * HALF / 4) / 256, 256>>>(latent, out);
}